// round 1
// baseline (speedup 1.0000x reference)
#include <cuda_runtime.h>

// Problem constants
#define Bn 32
#define Dn 1024
#define Hn 1024
#define BETA 0.9f

// Output layout (concatenated in reference return order):
//   [0, B*H)                      out   = tanh(a)
//   [B*H, 2*B*H)                  u_new = a
//   [2*B*H, 2*B*H + B*D*H)        E_w_new = 0.9*E_w + x[i,d]  (broadcast over h)
//   [2*B*H + B*D*H, ...)          E_b_new = 0.9*E_b + 1
//
// a[i,h] = 0.9*u[i,h] + sum_d x[i,d]*w[d,h] + b[h]

#define NB_GEMM 128                       // 32 i-rows * 4 h-chunks of 256
#define NB_EW   4096                      // 33554432 floats / (256 thr * 8 f4 * 4)
#define OFF_UNEW   (Bn*Hn)
#define OFF_EW     (2*Bn*Hn)
#define OFF_EB     (2*Bn*Hn + Bn*Dn*Hn)

__global__ void __launch_bounds__(256, 8)
diag_rtrl_kernel(const float* __restrict__ x,
                 const float* __restrict__ w,
                 const float* __restrict__ b,
                 const float* __restrict__ u,
                 const float* __restrict__ E_w,
                 const float* __restrict__ E_b,
                 float* __restrict__ out)
{
    const int bid = blockIdx.x;
    const int t   = threadIdx.x;

    if (bid < NB_GEMM) {
        // ---- GEMM + tanh + u_new + E_b path ----
        __shared__ float xs[Dn];
        const int i     = bid >> 2;          // batch row
        const int hbase = (bid & 3) * 256;   // h chunk

        // cooperative load of x[i, :] (1024 floats) via float4
        const float4* xr  = reinterpret_cast<const float4*>(x + i * Dn);
        reinterpret_cast<float4*>(xs)[t] = xr[t];
        __syncthreads();

        const int h = hbase + t;
        const float* wc = w + h;             // column h, stride Hn
        float acc = 0.0f;
        #pragma unroll 8
        for (int d = 0; d < Dn; ++d) {
            acc = fmaf(xs[d], __ldg(wc + d * Hn), acc);
        }

        const int ih = i * Hn + h;
        const float a = fmaf(BETA, u[ih], acc + b[h]);
        out[ih]            = tanhf(a);           // out
        out[OFF_UNEW + ih] = a;                  // u_new
        out[OFF_EB   + ih] = fmaf(BETA, E_b[ih], 1.0f);  // E_b_new
    } else {
        // ---- E_w streaming path: E_w_new = 0.9*E_w + x[row] ----
        // One block handles 8 contiguous rows of H=1024 floats (2048 float4s).
        const int eb = bid - NB_GEMM;                 // 0..4095
        const float4* e4 = reinterpret_cast<const float4*>(E_w);
        float4*       o4 = reinterpret_cast<float4*>(out + OFF_EW);
        const size_t base = (size_t)eb * 2048;        // float4 index

        #pragma unroll
        for (int k = 0; k < 8; ++k) {
            const size_t j = base + (size_t)k * 256 + t;
            const int row = (int)(j >> 8);            // i*D + d  (x flat index)
            const float xv = __ldg(x + row);          // uniform within block-iter
            float4 e = e4[j];
            float4 r;
            r.x = fmaf(BETA, e.x, xv);
            r.y = fmaf(BETA, e.y, xv);
            r.z = fmaf(BETA, e.z, xv);
            r.w = fmaf(BETA, e.w, xv);
            o4[j] = r;
        }
    }
}

extern "C" void kernel_launch(void* const* d_in, const int* in_sizes, int n_in,
                              void* d_out, int out_size)
{
    const float* x   = (const float*)d_in[0];   // [32,1024]
    const float* w   = (const float*)d_in[1];   // [1024,1024]
    const float* b   = (const float*)d_in[2];   // [1024]
    const float* u   = (const float*)d_in[3];   // [32,1024]
    const float* E_w = (const float*)d_in[4];   // [1,32,1024,1024]
    const float* E_b = (const float*)d_in[5];   // [1,32,1024]
    float* out = (float*)d_out;

    diag_rtrl_kernel<<<NB_GEMM + NB_EW, 256>>>(x, w, b, u, E_w, E_b, out);
}

// round 2
// speedup vs baseline: 2.2591x; 2.2591x over previous
#include <cuda_runtime.h>

// Problem constants
#define Bn 32
#define Dn 1024
#define Hn 1024
#define BETA 0.9f

// Output layout (concatenated in reference return order):
//   [0, B*H)                      out   = tanh(a)
//   [B*H, 2*B*H)                  u_new = a
//   [2*B*H, 2*B*H + B*D*H)        E_w_new = 0.9*E_w + x[i,d]  (broadcast over h)
//   [2*B*H + B*D*H, ...)          E_b_new = 0.9*E_b + 1

#define NB_GEMM 128                       // 32 i-rows * 4 h-chunks of 256
#define NB_EW   4096                      // 8 rows (of 1024 floats) per block
#define OFF_UNEW   (Bn*Hn)
#define OFF_EW     (2*Bn*Hn)
#define OFF_EB     (2*Bn*Hn + Bn*Dn*Hn)

__global__ void __launch_bounds__(256)
diag_rtrl_kernel(const float* __restrict__ x,
                 const float* __restrict__ w,
                 const float* __restrict__ b,
                 const float* __restrict__ u,
                 const float* __restrict__ E_w,
                 const float* __restrict__ E_b,
                 float* __restrict__ out)
{
    const int bid = blockIdx.x;
    const int t   = threadIdx.x;

    if (bid < NB_GEMM) {
        // ---- GEMM + tanh + u_new + E_b path ----
        __shared__ float xs[Dn];
        const int i     = bid >> 2;          // batch row
        const int hbase = (bid & 3) * 256;   // h chunk

        const float4* xr  = reinterpret_cast<const float4*>(x + i * Dn);
        reinterpret_cast<float4*>(xs)[t] = xr[t];
        __syncthreads();

        const int h = hbase + t;
        const float* wc = w + h;             // column h, stride Hn
        float acc = 0.0f;
        #pragma unroll 8
        for (int d = 0; d < Dn; ++d) {
            acc = fmaf(xs[d], __ldg(wc + d * Hn), acc);
        }

        const int ih = i * Hn + h;
        const float a = fmaf(BETA, u[ih], acc + b[h]);
        out[ih]            = tanhf(a);                   // out
        out[OFF_UNEW + ih] = a;                          // u_new
        out[OFF_EB   + ih] = fmaf(BETA, E_b[ih], 1.0f);  // E_b_new
    } else {
        // ---- E_w streaming: E_w_new = 0.9*E_w + x[row], row = flat(i,d) ----
        // Block handles 8 contiguous rows of H=1024 floats = 2048 float4s.
        // Phase 1: issue all 8 independent loads (MLP=8), then compute+store.
        const int eb = bid - NB_GEMM;                 // 0..4095
        const float4* e4 = reinterpret_cast<const float4*>(E_w);
        float4*       o4 = reinterpret_cast<float4*>(out + OFF_EW);
        const size_t base = (size_t)eb * 2048 + t;    // float4 index for k=0

        // x values for the 8 rows this block covers (uniform per k)
        float xv[8];
        #pragma unroll
        for (int k = 0; k < 8; ++k) xv[k] = __ldg(x + eb * 8 + k);

        float4 e[8];
        #pragma unroll
        for (int k = 0; k < 8; ++k)
            e[k] = __ldcs(e4 + base + (size_t)k * 256);

        #pragma unroll
        for (int k = 0; k < 8; ++k) {
            float4 r;
            r.x = fmaf(BETA, e[k].x, xv[k]);
            r.y = fmaf(BETA, e[k].y, xv[k]);
            r.z = fmaf(BETA, e[k].z, xv[k]);
            r.w = fmaf(BETA, e[k].w, xv[k]);
            __stcs(o4 + base + (size_t)k * 256, r);
        }
    }
}

extern "C" void kernel_launch(void* const* d_in, const int* in_sizes, int n_in,
                              void* d_out, int out_size)
{
    const float* x   = (const float*)d_in[0];   // [32,1024]
    const float* w   = (const float*)d_in[1];   // [1024,1024]
    const float* b   = (const float*)d_in[2];   // [1024]
    const float* u   = (const float*)d_in[3];   // [32,1024]
    const float* E_w = (const float*)d_in[4];   // [1,32,1024,1024]
    const float* E_b = (const float*)d_in[5];   // [1,32,1024]
    float* out = (float*)d_out;

    diag_rtrl_kernel<<<NB_GEMM + NB_EW, 256>>>(x, w, b, u, E_w, E_b, out);
}

// round 3
// speedup vs baseline: 2.7752x; 1.2285x over previous
#include <cuda_runtime.h>

// Problem constants
#define Bn 32
#define Dn 1024
#define Hn 1024
#define BETA 0.9f

// Output layout (concatenated in reference return order):
//   [0, B*H)                      out   = tanh(a)
//   [B*H, 2*B*H)                  u_new = a
//   [2*B*H, 2*B*H + B*D*H)        E_w_new = 0.9*E_w + x[i,d]  (broadcast over h)
//   [2*B*H + B*D*H, ...)          E_b_new = 0.9*E_b + 1

#define NB_GEMM 128                       // 32 i-rows * 4 h-chunks of 256
#define NB_EW   2048                      // 16 rows (of 1024 floats) per block
#define OFF_UNEW   (Bn*Hn)
#define OFF_EW     (2*Bn*Hn)
#define OFF_EB     (2*Bn*Hn + Bn*Dn*Hn)

__global__ void __launch_bounds__(256)
diag_rtrl_kernel(const float* __restrict__ x,
                 const float* __restrict__ w,
                 const float* __restrict__ b,
                 const float* __restrict__ u,
                 const float* __restrict__ E_w,
                 const float* __restrict__ E_b,
                 float* __restrict__ out)
{
    const int bid = blockIdx.x;
    const int t   = threadIdx.x;

    if (bid < NB_GEMM) {
        // ---- GEMM + tanh + u_new + E_b path ----
        __shared__ float xs[Dn];
        const int i     = bid >> 2;          // batch row
        const int hbase = (bid & 3) * 256;   // h chunk

        const float4* xr  = reinterpret_cast<const float4*>(x + i * Dn);
        reinterpret_cast<float4*>(xs)[t] = xr[t];
        __syncthreads();

        const int h = hbase + t;
        const float* wc = w + h;             // column h, stride Hn
        float acc = 0.0f;
        #pragma unroll 16
        for (int d = 0; d < Dn; ++d) {
            acc = fmaf(xs[d], __ldg(wc + d * Hn), acc);
        }

        const int ih = i * Hn + h;
        const float a = fmaf(BETA, u[ih], acc + b[h]);
        out[ih]            = tanhf(a);                   // out
        out[OFF_UNEW + ih] = a;                          // u_new
        out[OFF_EB   + ih] = fmaf(BETA, E_b[ih], 1.0f);  // E_b_new
    } else {
        // ---- E_w streaming: E_w_new = 0.9*E_w + x[row], row = flat(i,d) ----
        // Block handles 16 contiguous rows of H=1024 floats = 4096 float4s.
        // Issue ALL 16 independent loads (MLP=16) before any store.
        const int eb = bid - NB_GEMM;                 // 0..2047
        const float4* e4 = reinterpret_cast<const float4*>(E_w);
        float4*       o4 = reinterpret_cast<float4*>(out + OFF_EW);
        const size_t base = (size_t)eb * 4096 + t;    // float4 index for k=0

        // x values for the 16 rows this block covers (uniform per k, L2-hit)
        float xv[16];
        #pragma unroll
        for (int k = 0; k < 16; ++k) xv[k] = __ldg(x + eb * 16 + k);

        float4 e[16];
        #pragma unroll
        for (int k = 0; k < 16; ++k)
            e[k] = __ldcs(e4 + base + (size_t)k * 256);

        #pragma unroll
        for (int k = 0; k < 16; ++k) {
            float4 r;
            r.x = fmaf(BETA, e[k].x, xv[k]);
            r.y = fmaf(BETA, e[k].y, xv[k]);
            r.z = fmaf(BETA, e[k].z, xv[k]);
            r.w = fmaf(BETA, e[k].w, xv[k]);
            __stcs(o4 + base + (size_t)k * 256, r);
        }
    }
}

extern "C" void kernel_launch(void* const* d_in, const int* in_sizes, int n_in,
                              void* d_out, int out_size)
{
    const float* x   = (const float*)d_in[0];   // [32,1024]
    const float* w   = (const float*)d_in[1];   // [1024,1024]
    const float* b   = (const float*)d_in[2];   // [1024]
    const float* u   = (const float*)d_in[3];   // [32,1024]
    const float* E_w = (const float*)d_in[4];   // [1,32,1024,1024]
    const float* E_b = (const float*)d_in[5];   // [1,32,1024]
    float* out = (float*)d_out;

    diag_rtrl_kernel<<<NB_GEMM + NB_EW, 256>>>(x, w, b, u, E_w, E_b, out);
}